// round 11
// baseline (speedup 1.0000x reference)
#include <cuda_runtime.h>

#define B  4
#define Qn 256
#define Kn 1024
#define Dd 512
#define Hh 128
#define DV 512

#define ROWS_ALL (B * Qn + B * Kn)          // 5120 projected rows total

__device__ float g_s[B * Qn * Kn];          // 4 MB raw scores
__device__ float g_p[B * Qn * Kn];          // 4 MB normalized probs
__device__ float g_pp[2][ROWS_ALL * Hh];    // 5 MB proj K-split partials
__device__ float g_po[4][B * Qn * DV];      // 8 MB pv K-split partials

__device__ __forceinline__ float ex2a(float x) {
    float r; asm("ex2.approx.f32 %0, %1;" : "=f"(r) : "f"(x)); return r;
}
__device__ __forceinline__ float tanha(float x) {
    float r; asm("tanh.approx.f32 %0, %1;" : "=f"(r) : "f"(x)); return r;
}

// ---------------------------------------------------------------------------
// Projection GEMM (unchanged): grid 640 x 128, micro 4x4, K-split 2.
// Partials land in g_pp[0/1]; score_kernel fuses the reduction on load.
// Row map: rows 0..1023 = qh (b*Qn+q), rows 1024..5119 = kh (1024 + b*Kn + k).
// ---------------------------------------------------------------------------
__global__ void proj_kernel(const float* __restrict__ Xq, const float* __restrict__ Wq,
                            const float* __restrict__ Xk, const float* __restrict__ Wk) {
    __shared__ float Xs[32 * 36];
    __shared__ float Ws[32 * 68];

    const int bid = blockIdx.x;
    const int rt  = bid >> 2;
    const int ht  = (bid >> 1) & 1;
    const int ks  = bid & 1;
    const int r0  = rt * 32;
    const int h0  = ht * 64;
    const int d0  = ks * 256;

    const float* Xbase = (r0 < B * Qn) ? (Xq + (size_t)r0 * Dd)
                                       : (Xk + (size_t)(r0 - B * Qn) * Dd);
    const float* W = (r0 < B * Qn) ? Wq : Wk;

    const int tid = threadIdx.x;
    const int tx  = tid & 15;
    const int ty  = tid >> 4;

    float acc[4][4];
#pragma unroll
    for (int r = 0; r < 4; r++)
#pragma unroll
        for (int c = 0; c < 4; c++) acc[r][c] = 0.0f;

    for (int s = 0; s < 8; s++) {
        const int ds = d0 + s * 32;
        __syncthreads();
#pragma unroll
        for (int i = 0; i < 2; i++) {
            int e = tid + 128 * i;
            int r = e >> 3, c4 = (e & 7) * 4;
            float4 xv = *(const float4*)&Xbase[(size_t)r * Dd + ds + c4];
            Xs[(c4 + 0) * 36 + r] = xv.x;
            Xs[(c4 + 1) * 36 + r] = xv.y;
            Xs[(c4 + 2) * 36 + r] = xv.z;
            Xs[(c4 + 3) * 36 + r] = xv.w;
        }
#pragma unroll
        for (int i = 0; i < 4; i++) {
            int e = tid + 128 * i;
            int h = e >> 3, c4 = (e & 7) * 4;
            float4 wv = *(const float4*)&W[(size_t)(h0 + h) * Dd + ds + c4];
            Ws[(c4 + 0) * 68 + h] = wv.x;
            Ws[(c4 + 1) * 68 + h] = wv.y;
            Ws[(c4 + 2) * 68 + h] = wv.z;
            Ws[(c4 + 3) * 68 + h] = wv.w;
        }
        __syncthreads();
#pragma unroll
        for (int dd = 0; dd < 32; dd++) {
            float4 xv = *(const float4*)&Xs[dd * 36 + ty * 4];
            float4 wv = *(const float4*)&Ws[dd * 68 + tx * 4];
            acc[0][0] += xv.x * wv.x; acc[0][1] += xv.x * wv.y;
            acc[0][2] += xv.x * wv.z; acc[0][3] += xv.x * wv.w;
            acc[1][0] += xv.y * wv.x; acc[1][1] += xv.y * wv.y;
            acc[1][2] += xv.y * wv.z; acc[1][3] += xv.y * wv.w;
            acc[2][0] += xv.z * wv.x; acc[2][1] += xv.z * wv.y;
            acc[2][2] += xv.z * wv.z; acc[2][3] += xv.z * wv.w;
            acc[3][0] += xv.w * wv.x; acc[3][1] += xv.w * wv.y;
            acc[3][2] += xv.w * wv.z; acc[3][3] += xv.w * wv.w;
        }
    }

    float* pp = g_pp[ks];
#pragma unroll
    for (int r = 0; r < 4; r++) {
        float4 o = make_float4(acc[r][0], acc[r][1], acc[r][2], acc[r][3]);
        *(float4*)&pp[(size_t)(r0 + ty * 4 + r) * Hh + h0 + tx * 4] = o;
    }
}

// ---------------------------------------------------------------------------
// Scores kernel with fused proj reduction (reads g_pp[0]+g_pp[1] on load).
// Grid = B*(Q/16)*(K/64) = 1024 CTAs, 256 threads. MUFU-bound inner loop.
// ---------------------------------------------------------------------------
__global__ void score_kernel(const int* __restrict__ vlens,
                             const float* __restrict__ w_v) {
    __shared__ float kh_s[Hh * 65];
    __shared__ float qh_s[16 * Hh];
    __shared__ float wv_s[Hh];

    const int bx = blockIdx.x;
    const int b  = bx >> 8;
    const int qt = (bx >> 4) & 15;
    const int kt = bx & 15;
    const int q0 = qt * 16;
    const int k0 = kt * 64;

    if (k0 >= vlens[b]) return;

    const int tid  = threadIdx.x;
    const int lane = tid & 31;
    const int w    = tid >> 5;

    // qh tile 16x128 = sum of two partials (rows b*Qn+q0 ..)
    {
        const float4* s0 = (const float4*)(g_pp[0] + (size_t)(b * Qn + q0) * Hh);
        const float4* s1 = (const float4*)(g_pp[1] + (size_t)(b * Qn + q0) * Hh);
#pragma unroll
        for (int i = 0; i < 2; i++) {
            int e = tid + 256 * i;
            float4 a = s0[e], c = s1[e];
            ((float4*)qh_s)[e] = make_float4(a.x + c.x, a.y + c.y, a.z + c.z, a.w + c.w);
        }
    }
    if (tid < Hh) wv_s[tid] = w_v[tid];

    // kh tile 64k x 128h = sum of partials, transposed into kh_s[h][k] (pad 65)
    {
        const size_t rbase = (size_t)(B * Qn + b * Kn + k0) * Hh;
        const float* k0g = g_pp[0] + rbase;
        const float* k1g = g_pp[1] + rbase;
#pragma unroll
        for (int i = 0; i < 8; i++) {
            int e  = tid + 256 * i;
            int kr = e >> 5;
            int h4 = (e & 31) * 4;
            float4 a = *(const float4*)&k0g[(size_t)kr * Hh + h4];
            float4 c = *(const float4*)&k1g[(size_t)kr * Hh + h4];
            kh_s[(h4 + 0) * 65 + kr] = a.x + c.x;
            kh_s[(h4 + 1) * 65 + kr] = a.y + c.y;
            kh_s[(h4 + 2) * 65 + kr] = a.z + c.z;
            kh_s[(h4 + 3) * 65 + kr] = a.w + c.w;
        }
    }
    __syncthreads();

    const float* q0p = qh_s + (2 * w) * Hh;
    const float* q1p = qh_s + (2 * w + 1) * Hh;

    float s00 = 0.f, s01 = 0.f, s10 = 0.f, s11 = 0.f;
#pragma unroll 4
    for (int h = 0; h < Hh; h++) {
        float ka = kh_s[h * 65 + lane];
        float kb = kh_s[h * 65 + lane + 32];
        float qa = q0p[h];
        float qb = q1p[h];
        float wvv = wv_s[h];
        s00 += wvv * tanha(qa + ka);
        s01 += wvv * tanha(qa + kb);
        s10 += wvv * tanha(qb + ka);
        s11 += wvv * tanha(qb + kb);
    }

    float* so = g_s + (size_t)(b * Qn + q0 + 2 * w) * Kn + k0;
    so[lane]           = s00;
    so[lane + 32]      = s01;
    so[Kn + lane]      = s10;
    so[Kn + lane + 32] = s11;
}

// ---------------------------------------------------------------------------
// Softmax v3: 4 warps per row; fully-masked 256-chunks are skipped entirely.
// A chunk starting >= vl never overlaps pv's read region [0, ceil(vl/16)*16),
// so skipped warps neither load nor store. Grid 512 x 256 (2 rows/CTA).
// ---------------------------------------------------------------------------
__global__ void softmax_kernel(const int* __restrict__ vlens) {
    __shared__ float red_m[2][4];
    __shared__ float red_z[2][4];

    const int tid  = threadIdx.x;
    const int lane = tid & 31;
    const int w    = tid >> 5;
    const int rl   = w >> 2;                 // local row 0..1
    const int wr   = w & 3;                  // warp within row
    const int row  = blockIdx.x * 2 + rl;    // 0..1023
    const int b    = row >> 8;
    const int vl   = vlens[b];
    const bool act = (wr * 256) < vl;        // chunk overlaps valid region

    const float* srow = g_s + (size_t)row * Kn + wr * 256;
    float e_[8];
    float m = -3.4e38f;
    if (act) {
#pragma unroll
        for (int t = 0; t < 8; t++) {
            int k = wr * 256 + t * 32 + lane;
            e_[t] = (k < vl) ? srow[t * 32 + lane] : -1e6f;
            m = fmaxf(m, e_[t]);
        }
#pragma unroll
        for (int o = 16; o > 0; o >>= 1) m = fmaxf(m, __shfl_xor_sync(0xffffffffu, m, o));
    }
    if (lane == 0) red_m[rl][wr] = m;
    __syncthreads();
    const float M = fmaxf(fmaxf(red_m[rl][0], red_m[rl][1]),
                          fmaxf(red_m[rl][2], red_m[rl][3]));

    float Z = 0.f;
    if (act) {
#pragma unroll
        for (int t = 0; t < 8; t++) {
            e_[t] = ex2a((e_[t] - M) * 1.4426950408889634f);
            Z += e_[t];
        }
#pragma unroll
        for (int o = 16; o > 0; o >>= 1) Z += __shfl_xor_sync(0xffffffffu, Z, o);
    }
    if (lane == 0) red_z[rl][wr] = Z;
    __syncthreads();

    if (act) {
        const float invZ = 1.0f / (((red_z[rl][0] + red_z[rl][1]) +
                                    (red_z[rl][2] + red_z[rl][3])));
        float* prow = g_p + (size_t)row * Kn + wr * 256;
#pragma unroll
        for (int t = 0; t < 8; t++) prow[t * 32 + lane] = e_[t] * invZ;
    }
}

// ---------------------------------------------------------------------------
// Partial P@V (unchanged): q-tile 32, 512 threads, 4-way parity K-split.
// Grid = B * (Q/32) * 2(dv) * 4(ks) = 256 CTAs.
// ---------------------------------------------------------------------------
__global__ void pv_kernel(const float* __restrict__ v, const int* __restrict__ vlens) {
    __shared__ __align__(16) float v_s[16 * 256];   // 16 KB
    __shared__ float p_s[32 * 16];                  // 2 KB

    const int bx  = blockIdx.x;
    const int ks  =  bx       & 3;
    const int dvs = (bx >> 2) & 1;
    const int qt  = (bx >> 3) & 7;
    const int b   =  bx >> 6;
    const int q0  = qt * 32;
    const int dv0 = dvs * 256;

    const int tid  = threadIdx.x;
    const int lane = tid & 31;
    const int w    = tid >> 5;
    const int vl   = vlens[b];

    const int qg  = (w & 7) * 4;
    const int dvh = (w >> 3) * 32;
    const int n3  = (vl + 15) >> 4;

    const float* vb = v + (size_t)b * Kn * DV + dv0;
    const float* pg = g_p + (size_t)(b * Qn + q0) * Kn;

    float4 vpre[2];
    float  ppre;
    {
        const int k0 = ks * 16;
#pragma unroll
        for (int i = 0; i < 2; i++) {
            int e = tid + 512 * i;
            vpre[i] = *(const float4*)&vb[(size_t)(k0 + (e >> 6)) * DV + (e & 63) * 4];
        }
        ppre = pg[(size_t)(tid >> 4) * Kn + k0 + (tid & 15)];
    }

    float4 acc[4];
#pragma unroll
    for (int r = 0; r < 4; r++) acc[r] = make_float4(0.f, 0.f, 0.f, 0.f);

    for (int t = ks; t < n3; t += 4) {
        __syncthreads();
#pragma unroll
        for (int i = 0; i < 2; i++) {
            int e = tid + 512 * i;
            *(float4*)&v_s[(e >> 6) * 256 + (e & 63) * 4] = vpre[i];
        }
        p_s[tid] = ppre;
        __syncthreads();
        if (t + 4 < n3) {
            const int kn = (t + 4) * 16;
#pragma unroll
            for (int i = 0; i < 2; i++) {
                int e = tid + 512 * i;
                vpre[i] = *(const float4*)&vb[(size_t)(kn + (e >> 6)) * DV + (e & 63) * 4];
            }
            ppre = pg[(size_t)(tid >> 4) * Kn + kn + (tid & 15)];
        }
#pragma unroll
        for (int kk = 0; kk < 16; kk++) {
            float4 vv = *(const float4*)&v_s[kk * 256 + (dvh + lane) * 4];
            float p0 = p_s[(qg + 0) * 16 + kk];
            float p1 = p_s[(qg + 1) * 16 + kk];
            float p2 = p_s[(qg + 2) * 16 + kk];
            float p3 = p_s[(qg + 3) * 16 + kk];
            acc[0].x += p0 * vv.x; acc[0].y += p0 * vv.y;
            acc[0].z += p0 * vv.z; acc[0].w += p0 * vv.w;
            acc[1].x += p1 * vv.x; acc[1].y += p1 * vv.y;
            acc[1].z += p1 * vv.z; acc[1].w += p1 * vv.w;
            acc[2].x += p2 * vv.x; acc[2].y += p2 * vv.y;
            acc[2].z += p2 * vv.z; acc[2].w += p2 * vv.w;
            acc[3].x += p3 * vv.x; acc[3].y += p3 * vv.y;
            acc[3].z += p3 * vv.z; acc[3].w += p3 * vv.w;
        }
    }

    float* po = g_po[ks];
#pragma unroll
    for (int r = 0; r < 4; r++)
        *(float4*)&po[(size_t)(b * Qn + q0 + qg + r) * DV + dv0 + (dvh + lane) * 4] = acc[r];
}

// ---------------------------------------------------------------------------
// Sum the 4 pv partials into the output, fixed order. 512 x 256.
// ---------------------------------------------------------------------------
__global__ void pv_reduce_kernel(float* __restrict__ out) {
    const int i = blockIdx.x * 256 + threadIdx.x;
    const float4 a = ((const float4*)g_po[0])[i];
    const float4 b = ((const float4*)g_po[1])[i];
    const float4 c = ((const float4*)g_po[2])[i];
    const float4 d = ((const float4*)g_po[3])[i];
    ((float4*)out)[i] = make_float4(((a.x + b.x) + (c.x + d.x)),
                                    ((a.y + b.y) + (c.y + d.y)),
                                    ((a.z + b.z) + (c.z + d.z)),
                                    ((a.w + b.w) + (c.w + d.w)));
}

// ---------------------------------------------------------------------------
extern "C" void kernel_launch(void* const* d_in, const int* in_sizes, int n_in,
                              void* d_out, int out_size) {
    const float* q    = (const float*)d_in[0];
    const float* k    = (const float*)d_in[1];
    const float* v    = (const float*)d_in[2];
    const int*   vlen = (const int*)d_in[3];
    const float* w_q  = (const float*)d_in[4];
    const float* w_k  = (const float*)d_in[5];
    const float* w_v  = (const float*)d_in[6];
    float*       out  = (float*)d_out;

    proj_kernel<<<640, 128>>>(q, w_q, k, w_k);
    score_kernel<<<1024, 256>>>(vlen, w_v);
    softmax_kernel<<<512, 256>>>(vlen);
    pv_kernel<<<256, 512>>>(v, vlen);
    pv_reduce_kernel<<<512, 256>>>(out);
}

// round 12
// speedup vs baseline: 1.5235x; 1.5235x over previous
#include <cuda_runtime.h>

#define B  4
#define Qn 256
#define Kn 1024
#define Dd 512
#define Hh 128
#define DV 512

#define ROWS_ALL (B * Qn + B * Kn)          // 5120 projected rows total

__device__ float g_qh[B * Qn * Hh];         // 512 KB
__device__ float g_kh[B * Kn * Hh];         // 2 MB
__device__ float g_s[B * Qn * Kn];          // 4 MB raw scores
__device__ float g_p[B * Qn * Kn];          // 4 MB normalized probs
__device__ float g_pp[2][ROWS_ALL * Hh];    // 5 MB proj K-split partials
__device__ float g_po[4][B * Qn * DV];      // 8 MB pv K-split partials

__device__ __forceinline__ float ex2a(float x) {
    float r; asm("ex2.approx.f32 %0, %1;" : "=f"(r) : "f"(x)); return r;
}
__device__ __forceinline__ float tanha(float x) {
    float r; asm("tanh.approx.f32 %0, %1;" : "=f"(r) : "f"(x)); return r;
}

// ---------------------------------------------------------------------------
// Projection GEMM (R9): grid 640 x 128, micro 4x4, K-split 2.
// ---------------------------------------------------------------------------
__global__ void proj_kernel(const float* __restrict__ Xq, const float* __restrict__ Wq,
                            const float* __restrict__ Xk, const float* __restrict__ Wk) {
    __shared__ float Xs[32 * 36];
    __shared__ float Ws[32 * 68];

    const int bid = blockIdx.x;
    const int rt  = bid >> 2;
    const int ht  = (bid >> 1) & 1;
    const int ks  = bid & 1;
    const int r0  = rt * 32;
    const int h0  = ht * 64;
    const int d0  = ks * 256;

    const float* Xbase = (r0 < B * Qn) ? (Xq + (size_t)r0 * Dd)
                                       : (Xk + (size_t)(r0 - B * Qn) * Dd);
    const float* W = (r0 < B * Qn) ? Wq : Wk;

    const int tid = threadIdx.x;
    const int tx  = tid & 15;
    const int ty  = tid >> 4;

    float acc[4][4];
#pragma unroll
    for (int r = 0; r < 4; r++)
#pragma unroll
        for (int c = 0; c < 4; c++) acc[r][c] = 0.0f;

    for (int s = 0; s < 8; s++) {
        const int ds = d0 + s * 32;
        __syncthreads();
#pragma unroll
        for (int i = 0; i < 2; i++) {
            int e = tid + 128 * i;
            int r = e >> 3, c4 = (e & 7) * 4;
            float4 xv = *(const float4*)&Xbase[(size_t)r * Dd + ds + c4];
            Xs[(c4 + 0) * 36 + r] = xv.x;
            Xs[(c4 + 1) * 36 + r] = xv.y;
            Xs[(c4 + 2) * 36 + r] = xv.z;
            Xs[(c4 + 3) * 36 + r] = xv.w;
        }
#pragma unroll
        for (int i = 0; i < 4; i++) {
            int e = tid + 128 * i;
            int h = e >> 3, c4 = (e & 7) * 4;
            float4 wv = *(const float4*)&W[(size_t)(h0 + h) * Dd + ds + c4];
            Ws[(c4 + 0) * 68 + h] = wv.x;
            Ws[(c4 + 1) * 68 + h] = wv.y;
            Ws[(c4 + 2) * 68 + h] = wv.z;
            Ws[(c4 + 3) * 68 + h] = wv.w;
        }
        __syncthreads();
#pragma unroll
        for (int dd = 0; dd < 32; dd++) {
            float4 xv = *(const float4*)&Xs[dd * 36 + ty * 4];
            float4 wv = *(const float4*)&Ws[dd * 68 + tx * 4];
            acc[0][0] += xv.x * wv.x; acc[0][1] += xv.x * wv.y;
            acc[0][2] += xv.x * wv.z; acc[0][3] += xv.x * wv.w;
            acc[1][0] += xv.y * wv.x; acc[1][1] += xv.y * wv.y;
            acc[1][2] += xv.y * wv.z; acc[1][3] += xv.y * wv.w;
            acc[2][0] += xv.z * wv.x; acc[2][1] += xv.z * wv.y;
            acc[2][2] += xv.z * wv.z; acc[2][3] += xv.z * wv.w;
            acc[3][0] += xv.w * wv.x; acc[3][1] += xv.w * wv.y;
            acc[3][2] += xv.w * wv.z; acc[3][3] += xv.w * wv.w;
        }
    }

    float* pp = g_pp[ks];
#pragma unroll
    for (int r = 0; r < 4; r++) {
        float4 o = make_float4(acc[r][0], acc[r][1], acc[r][2], acc[r][3]);
        *(float4*)&pp[(size_t)(r0 + ty * 4 + r) * Hh + h0 + tx * 4] = o;
    }
}

__global__ void proj_reduce_kernel() {
    const int i = blockIdx.x * 256 + threadIdx.x;
    const float4 a = ((const float4*)g_pp[0])[i];
    const float4 b = ((const float4*)g_pp[1])[i];
    float4 o = make_float4(a.x + b.x, a.y + b.y, a.z + b.z, a.w + b.w);
    const int qlim = (B * Qn * Hh) / 4;
    if (i < qlim) ((float4*)g_qh)[i] = o;
    else          ((float4*)g_kh)[i - qlim] = o;
}

// ---------------------------------------------------------------------------
// Scores kernel (R9; at MUFU floor). Grid = 1024 CTAs, 256 threads.
// ---------------------------------------------------------------------------
__global__ void score_kernel(const int* __restrict__ vlens,
                             const float* __restrict__ w_v) {
    __shared__ float kh_s[Hh * 65];
    __shared__ float qh_s[16 * Hh];
    __shared__ float wv_s[Hh];

    const int bx = blockIdx.x;
    const int b  = bx >> 8;
    const int qt = (bx >> 4) & 15;
    const int kt = bx & 15;
    const int q0 = qt * 16;
    const int k0 = kt * 64;

    if (k0 >= vlens[b]) return;

    const int tid  = threadIdx.x;
    const int lane = tid & 31;
    const int w    = tid >> 5;

    {
        const float4* src = (const float4*)(g_qh + (size_t)(b * Qn + q0) * Hh);
        ((float4*)qh_s)[tid]       = src[tid];
        ((float4*)qh_s)[tid + 256] = src[tid + 256];
    }
    if (tid < Hh) wv_s[tid] = w_v[tid];

    {
        const float* khg = g_kh + (size_t)(b * Kn + k0) * Hh;
#pragma unroll
        for (int i = 0; i < 8; i++) {
            int e  = tid + 256 * i;
            int kr = e >> 5;
            int h4 = (e & 31) * 4;
            float4 vv = *(const float4*)&khg[(size_t)kr * Hh + h4];
            kh_s[(h4 + 0) * 65 + kr] = vv.x;
            kh_s[(h4 + 1) * 65 + kr] = vv.y;
            kh_s[(h4 + 2) * 65 + kr] = vv.z;
            kh_s[(h4 + 3) * 65 + kr] = vv.w;
        }
    }
    __syncthreads();

    const float* q0p = qh_s + (2 * w) * Hh;
    const float* q1p = qh_s + (2 * w + 1) * Hh;

    float s00 = 0.f, s01 = 0.f, s10 = 0.f, s11 = 0.f;
#pragma unroll 4
    for (int h = 0; h < Hh; h++) {
        float ka = kh_s[h * 65 + lane];
        float kb = kh_s[h * 65 + lane + 32];
        float qa = q0p[h];
        float qb = q1p[h];
        float wvv = wv_s[h];
        s00 += wvv * tanha(qa + ka);
        s01 += wvv * tanha(qa + kb);
        s10 += wvv * tanha(qb + ka);
        s11 += wvv * tanha(qb + kb);
    }

    float* so = g_s + (size_t)(b * Qn + q0 + 2 * w) * Kn + k0;
    so[lane]           = s00;
    so[lane + 32]      = s01;
    so[Kn + lane]      = s10;
    so[Kn + lane + 32] = s11;
}

// ---------------------------------------------------------------------------
// Softmax (R9 v1 + trimmed stores): warp per q row. Grid 256 x 128.
// Stores only k < ceil(vl/16)*16 — the exact region pv reads; dropped
// entries were all exact zeros (exp underflow), so results are unchanged.
// ---------------------------------------------------------------------------
__global__ void softmax_kernel(const int* __restrict__ vlens) {
    const int row  = blockIdx.x * 4 + (threadIdx.x >> 5);   // 0..1023
    const int lane = threadIdx.x & 31;
    const int b    = row >> 8;
    const int vl   = vlens[b];
    const int lim  = (vl + 15) & ~15;        // pv read bound

    const float* srow = g_s + (size_t)row * Kn;
    float e_[32];
    float m = -3.4e38f;
#pragma unroll
    for (int t = 0; t < 32; t++) {
        int k = t * 32 + lane;
        e_[t] = (k < vl) ? srow[k] : -1e6f;
        m = fmaxf(m, e_[t]);
    }
#pragma unroll
    for (int o = 16; o > 0; o >>= 1) m = fmaxf(m, __shfl_xor_sync(0xffffffffu, m, o));
    float Z = 0.f;
#pragma unroll
    for (int t = 0; t < 32; t++) {
        e_[t] = ex2a((e_[t] - m) * 1.4426950408889634f);
        Z += e_[t];
    }
#pragma unroll
    for (int o = 16; o > 0; o >>= 1) Z += __shfl_xor_sync(0xffffffffu, Z, o);
    const float invZ = 1.0f / Z;

    float* prow = g_p + (size_t)row * Kn;
#pragma unroll
    for (int t = 0; t < 32; t++) {
        if (t * 32 < lim) prow[t * 32 + lane] = e_[t] * invZ;
    }
}

// ---------------------------------------------------------------------------
// Partial P@V (R9): q-tile 16, 256 threads, 4-way parity K-split.
// Grid = B * (Q/16) * 2(dv) * 4(ks) = 512 CTAs.
// ---------------------------------------------------------------------------
__global__ void pv_kernel(const float* __restrict__ v, const int* __restrict__ vlens) {
    __shared__ __align__(16) float v_s[16 * 256];   // 16 KB
    __shared__ float p_s[16 * 16];                  // 1 KB

    const int bx  = blockIdx.x;
    const int ks  =  bx       & 3;
    const int dvs = (bx >> 2) & 1;
    const int qt  = (bx >> 3) & 15;
    const int b   =  bx >> 7;
    const int q0  = qt * 16;
    const int dv0 = dvs * 256;

    const int tid  = threadIdx.x;
    const int lane = tid & 31;
    const int w    = tid >> 5;
    const int vl   = vlens[b];

    const int qg  = (w & 3) * 4;
    const int dvh = (w >> 2) * 32;
    const int n3  = (vl + 15) >> 4;

    const float* vb = v + (size_t)b * Kn * DV + dv0;
    const float* pg = g_p + (size_t)(b * Qn + q0) * Kn;

    float4 vpre[4];
    float  ppre;
    {
        const int k0 = ks * 16;
#pragma unroll
        for (int i = 0; i < 4; i++) {
            int e = tid + 256 * i;
            vpre[i] = *(const float4*)&vb[(size_t)(k0 + (e >> 6)) * DV + (e & 63) * 4];
        }
        ppre = pg[(size_t)(tid >> 4) * Kn + k0 + (tid & 15)];
    }

    float4 acc[4];
#pragma unroll
    for (int r = 0; r < 4; r++) acc[r] = make_float4(0.f, 0.f, 0.f, 0.f);

    for (int t = ks; t < n3; t += 4) {
        __syncthreads();
#pragma unroll
        for (int i = 0; i < 4; i++) {
            int e = tid + 256 * i;
            *(float4*)&v_s[(e >> 6) * 256 + (e & 63) * 4] = vpre[i];
        }
        p_s[(tid >> 4) * 16 + (tid & 15)] = ppre;
        __syncthreads();
        if (t + 4 < n3) {
            const int kn = (t + 4) * 16;
#pragma unroll
            for (int i = 0; i < 4; i++) {
                int e = tid + 256 * i;
                vpre[i] = *(const float4*)&vb[(size_t)(kn + (e >> 6)) * DV + (e & 63) * 4];
            }
            ppre = pg[(size_t)(tid >> 4) * Kn + kn + (tid & 15)];
        }
#pragma unroll
        for (int kk = 0; kk < 16; kk++) {
            float4 vv = *(const float4*)&v_s[kk * 256 + (dvh + lane) * 4];
            float p0 = p_s[(qg + 0) * 16 + kk];
            float p1 = p_s[(qg + 1) * 16 + kk];
            float p2 = p_s[(qg + 2) * 16 + kk];
            float p3 = p_s[(qg + 3) * 16 + kk];
            acc[0].x += p0 * vv.x; acc[0].y += p0 * vv.y;
            acc[0].z += p0 * vv.z; acc[0].w += p0 * vv.w;
            acc[1].x += p1 * vv.x; acc[1].y += p1 * vv.y;
            acc[1].z += p1 * vv.z; acc[1].w += p1 * vv.w;
            acc[2].x += p2 * vv.x; acc[2].y += p2 * vv.y;
            acc[2].z += p2 * vv.z; acc[2].w += p2 * vv.w;
            acc[3].x += p3 * vv.x; acc[3].y += p3 * vv.y;
            acc[3].z += p3 * vv.z; acc[3].w += p3 * vv.w;
        }
    }

    float* po = g_po[ks];
#pragma unroll
    for (int r = 0; r < 4; r++)
        *(float4*)&po[(size_t)(b * Qn + q0 + qg + r) * DV + dv0 + (dvh + lane) * 4] = acc[r];
}

// ---------------------------------------------------------------------------
// Sum the 4 pv partials into the output, fixed order. 512 x 256.
// ---------------------------------------------------------------------------
__global__ void pv_reduce_kernel(float* __restrict__ out) {
    const int i = blockIdx.x * 256 + threadIdx.x;
    const float4 a = ((const float4*)g_po[0])[i];
    const float4 b = ((const float4*)g_po[1])[i];
    const float4 c = ((const float4*)g_po[2])[i];
    const float4 d = ((const float4*)g_po[3])[i];
    ((float4*)out)[i] = make_float4(((a.x + b.x) + (c.x + d.x)),
                                    ((a.y + b.y) + (c.y + d.y)),
                                    ((a.z + b.z) + (c.z + d.z)),
                                    ((a.w + b.w) + (c.w + d.w)));
}

// ---------------------------------------------------------------------------
extern "C" void kernel_launch(void* const* d_in, const int* in_sizes, int n_in,
                              void* d_out, int out_size) {
    const float* q    = (const float*)d_in[0];
    const float* k    = (const float*)d_in[1];
    const float* v    = (const float*)d_in[2];
    const int*   vlen = (const int*)d_in[3];
    const float* w_q  = (const float*)d_in[4];
    const float* w_k  = (const float*)d_in[5];
    const float* w_v  = (const float*)d_in[6];
    float*       out  = (float*)d_out;

    proj_kernel<<<640, 128>>>(q, w_q, k, w_k);
    proj_reduce_kernel<<<640, 256>>>();
    score_kernel<<<1024, 256>>>(vlen, w_v);
    softmax_kernel<<<256, 128>>>(vlen);
    pv_kernel<<<512, 256>>>(v, vlen);
    pv_reduce_kernel<<<512, 256>>>(out);
}

// round 13
// speedup vs baseline: 1.5323x; 1.0058x over previous
#include <cuda_runtime.h>

#define B  4
#define Qn 256
#define Kn 1024
#define Dd 512
#define Hh 128
#define DV 512

#define ROWS_ALL (B * Qn + B * Kn)          // 5120 projected rows total

__device__ float g_qh[B * Qn * Hh];         // 512 KB
__device__ float g_kh[B * Kn * Hh];         // 2 MB
__device__ float g_s[B * Qn * Kn];          // 4 MB raw scores
__device__ float g_p[B * Qn * Kn];          // 4 MB normalized probs
__device__ float g_pp[2][ROWS_ALL * Hh];    // 5 MB proj K-split partials
__device__ float g_po[4][B * Qn * DV];      // 8 MB pv K-split partials
__device__ int   g_cnt[B * 16 * 2];         // pv group arrival counters (zero-init)

__device__ __forceinline__ float ex2a(float x) {
    float r; asm("ex2.approx.f32 %0, %1;" : "=f"(r) : "f"(x)); return r;
}
__device__ __forceinline__ float tanha(float x) {
    float r; asm("tanh.approx.f32 %0, %1;" : "=f"(r) : "f"(x)); return r;
}

// ---------------------------------------------------------------------------
// Projection GEMM (R9): grid 640 x 128, micro 4x4, K-split 2.
// ---------------------------------------------------------------------------
__global__ void proj_kernel(const float* __restrict__ Xq, const float* __restrict__ Wq,
                            const float* __restrict__ Xk, const float* __restrict__ Wk) {
    __shared__ float Xs[32 * 36];
    __shared__ float Ws[32 * 68];

    const int bid = blockIdx.x;
    const int rt  = bid >> 2;
    const int ht  = (bid >> 1) & 1;
    const int ks  = bid & 1;
    const int r0  = rt * 32;
    const int h0  = ht * 64;
    const int d0  = ks * 256;

    const float* Xbase = (r0 < B * Qn) ? (Xq + (size_t)r0 * Dd)
                                       : (Xk + (size_t)(r0 - B * Qn) * Dd);
    const float* W = (r0 < B * Qn) ? Wq : Wk;

    const int tid = threadIdx.x;
    const int tx  = tid & 15;
    const int ty  = tid >> 4;

    float acc[4][4];
#pragma unroll
    for (int r = 0; r < 4; r++)
#pragma unroll
        for (int c = 0; c < 4; c++) acc[r][c] = 0.0f;

    for (int s = 0; s < 8; s++) {
        const int ds = d0 + s * 32;
        __syncthreads();
#pragma unroll
        for (int i = 0; i < 2; i++) {
            int e = tid + 128 * i;
            int r = e >> 3, c4 = (e & 7) * 4;
            float4 xv = *(const float4*)&Xbase[(size_t)r * Dd + ds + c4];
            Xs[(c4 + 0) * 36 + r] = xv.x;
            Xs[(c4 + 1) * 36 + r] = xv.y;
            Xs[(c4 + 2) * 36 + r] = xv.z;
            Xs[(c4 + 3) * 36 + r] = xv.w;
        }
#pragma unroll
        for (int i = 0; i < 4; i++) {
            int e = tid + 128 * i;
            int h = e >> 3, c4 = (e & 7) * 4;
            float4 wv = *(const float4*)&W[(size_t)(h0 + h) * Dd + ds + c4];
            Ws[(c4 + 0) * 68 + h] = wv.x;
            Ws[(c4 + 1) * 68 + h] = wv.y;
            Ws[(c4 + 2) * 68 + h] = wv.z;
            Ws[(c4 + 3) * 68 + h] = wv.w;
        }
        __syncthreads();
#pragma unroll
        for (int dd = 0; dd < 32; dd++) {
            float4 xv = *(const float4*)&Xs[dd * 36 + ty * 4];
            float4 wv = *(const float4*)&Ws[dd * 68 + tx * 4];
            acc[0][0] += xv.x * wv.x; acc[0][1] += xv.x * wv.y;
            acc[0][2] += xv.x * wv.z; acc[0][3] += xv.x * wv.w;
            acc[1][0] += xv.y * wv.x; acc[1][1] += xv.y * wv.y;
            acc[1][2] += xv.y * wv.z; acc[1][3] += xv.y * wv.w;
            acc[2][0] += xv.z * wv.x; acc[2][1] += xv.z * wv.y;
            acc[2][2] += xv.z * wv.z; acc[2][3] += xv.z * wv.w;
            acc[3][0] += xv.w * wv.x; acc[3][1] += xv.w * wv.y;
            acc[3][2] += xv.w * wv.z; acc[3][3] += xv.w * wv.w;
        }
    }

    float* pp = g_pp[ks];
#pragma unroll
    for (int r = 0; r < 4; r++) {
        float4 o = make_float4(acc[r][0], acc[r][1], acc[r][2], acc[r][3]);
        *(float4*)&pp[(size_t)(r0 + ty * 4 + r) * Hh + h0 + tx * 4] = o;
    }
}

__global__ void proj_reduce_kernel() {
    const int i = blockIdx.x * 256 + threadIdx.x;
    const float4 a = ((const float4*)g_pp[0])[i];
    const float4 b = ((const float4*)g_pp[1])[i];
    float4 o = make_float4(a.x + b.x, a.y + b.y, a.z + b.z, a.w + b.w);
    const int qlim = (B * Qn * Hh) / 4;
    if (i < qlim) ((float4*)g_qh)[i] = o;
    else          ((float4*)g_kh)[i - qlim] = o;
}

// ---------------------------------------------------------------------------
// Scores kernel (R9; at MUFU floor). Grid = 1024 CTAs, 256 threads.
// ---------------------------------------------------------------------------
__global__ void score_kernel(const int* __restrict__ vlens,
                             const float* __restrict__ w_v) {
    __shared__ float kh_s[Hh * 65];
    __shared__ float qh_s[16 * Hh];
    __shared__ float wv_s[Hh];

    const int bx = blockIdx.x;
    const int b  = bx >> 8;
    const int qt = (bx >> 4) & 15;
    const int kt = bx & 15;
    const int q0 = qt * 16;
    const int k0 = kt * 64;

    if (k0 >= vlens[b]) return;

    const int tid  = threadIdx.x;
    const int lane = tid & 31;
    const int w    = tid >> 5;

    {
        const float4* src = (const float4*)(g_qh + (size_t)(b * Qn + q0) * Hh);
        ((float4*)qh_s)[tid]       = src[tid];
        ((float4*)qh_s)[tid + 256] = src[tid + 256];
    }
    if (tid < Hh) wv_s[tid] = w_v[tid];

    {
        const float* khg = g_kh + (size_t)(b * Kn + k0) * Hh;
#pragma unroll
        for (int i = 0; i < 8; i++) {
            int e  = tid + 256 * i;
            int kr = e >> 5;
            int h4 = (e & 31) * 4;
            float4 vv = *(const float4*)&khg[(size_t)kr * Hh + h4];
            kh_s[(h4 + 0) * 65 + kr] = vv.x;
            kh_s[(h4 + 1) * 65 + kr] = vv.y;
            kh_s[(h4 + 2) * 65 + kr] = vv.z;
            kh_s[(h4 + 3) * 65 + kr] = vv.w;
        }
    }
    __syncthreads();

    const float* q0p = qh_s + (2 * w) * Hh;
    const float* q1p = qh_s + (2 * w + 1) * Hh;

    float s00 = 0.f, s01 = 0.f, s10 = 0.f, s11 = 0.f;
#pragma unroll 4
    for (int h = 0; h < Hh; h++) {
        float ka = kh_s[h * 65 + lane];
        float kb = kh_s[h * 65 + lane + 32];
        float qa = q0p[h];
        float qb = q1p[h];
        float wvv = wv_s[h];
        s00 += wvv * tanha(qa + ka);
        s01 += wvv * tanha(qa + kb);
        s10 += wvv * tanha(qb + ka);
        s11 += wvv * tanha(qb + kb);
    }

    float* so = g_s + (size_t)(b * Qn + q0 + 2 * w) * Kn + k0;
    so[lane]           = s00;
    so[lane + 32]      = s01;
    so[Kn + lane]      = s10;
    so[Kn + lane + 32] = s11;
}

// ---------------------------------------------------------------------------
// Softmax (R12): warp per q row, stores trimmed to pv's read region.
// ---------------------------------------------------------------------------
__global__ void softmax_kernel(const int* __restrict__ vlens) {
    const int row  = blockIdx.x * 4 + (threadIdx.x >> 5);   // 0..1023
    const int lane = threadIdx.x & 31;
    const int b    = row >> 8;
    const int vl   = vlens[b];
    const int lim  = (vl + 15) & ~15;        // pv read bound

    const float* srow = g_s + (size_t)row * Kn;
    float e_[32];
    float m = -3.4e38f;
#pragma unroll
    for (int t = 0; t < 32; t++) {
        int k = t * 32 + lane;
        e_[t] = (k < vl) ? srow[k] : -1e6f;
        m = fmaxf(m, e_[t]);
    }
#pragma unroll
    for (int o = 16; o > 0; o >>= 1) m = fmaxf(m, __shfl_xor_sync(0xffffffffu, m, o));
    float Z = 0.f;
#pragma unroll
    for (int t = 0; t < 32; t++) {
        e_[t] = ex2a((e_[t] - m) * 1.4426950408889634f);
        Z += e_[t];
    }
#pragma unroll
    for (int o = 16; o > 0; o >>= 1) Z += __shfl_xor_sync(0xffffffffu, Z, o);
    const float invZ = 1.0f / Z;

    float* prow = g_p + (size_t)row * Kn;
#pragma unroll
    for (int t = 0; t < 32; t++) {
        if (t * 32 < lim) prow[t * 32 + lane] = e_[t] * invZ;
    }
}

// ---------------------------------------------------------------------------
// Partial P@V with register-staged float4 p + fused last-CTA reduction.
// Grid = B * (Q/16) * 2(dv) * 4(ks) = 512 CTAs, 256 threads (8 warps).
// The 4 ks CTAs of a group arrive on g_cnt; the last sums g_po[0..3] in
// FIXED order into out (deterministic) and resets the counter (replay-safe).
// ---------------------------------------------------------------------------
__global__ void pv_kernel(const float* __restrict__ v, const int* __restrict__ vlens,
                          float* __restrict__ out) {
    __shared__ __align__(16) float v_s[16 * 256];   // 16 KB
    __shared__ __align__(16) float p_s[16 * 16];    // 1 KB
    __shared__ int last_s;

    const int bx  = blockIdx.x;
    const int ks  =  bx       & 3;
    const int dvs = (bx >> 2) & 1;
    const int qt  = (bx >> 3) & 15;
    const int b   =  bx >> 7;
    const int q0  = qt * 16;
    const int dv0 = dvs * 256;
    const int grp = bx >> 2;                        // 0..127

    const int tid  = threadIdx.x;
    const int lane = tid & 31;
    const int w    = tid >> 5;
    const int vl   = vlens[b];

    const int qg  = (w & 3) * 4;
    const int dvh = (w >> 2) * 32;
    const int n3  = (vl + 15) >> 4;

    const float* vb = v + (size_t)b * Kn * DV + dv0;
    const float* pg = g_p + (size_t)(b * Qn + q0) * Kn;

    float4 vpre[4];
    float  ppre;
    {
        const int k0 = ks * 16;
#pragma unroll
        for (int i = 0; i < 4; i++) {
            int e = tid + 256 * i;
            vpre[i] = *(const float4*)&vb[(size_t)(k0 + (e >> 6)) * DV + (e & 63) * 4];
        }
        ppre = pg[(size_t)(tid >> 4) * Kn + k0 + (tid & 15)];
    }

    float4 acc[4];
#pragma unroll
    for (int r = 0; r < 4; r++) acc[r] = make_float4(0.f, 0.f, 0.f, 0.f);

    for (int t = ks; t < n3; t += 4) {
        __syncthreads();
#pragma unroll
        for (int i = 0; i < 4; i++) {
            int e = tid + 256 * i;
            *(float4*)&v_s[(e >> 6) * 256 + (e & 63) * 4] = vpre[i];
        }
        p_s[(tid >> 4) * 16 + (tid & 15)] = ppre;
        __syncthreads();
        if (t + 4 < n3) {
            const int kn = (t + 4) * 16;
#pragma unroll
            for (int i = 0; i < 4; i++) {
                int e = tid + 256 * i;
                vpre[i] = *(const float4*)&vb[(size_t)(kn + (e >> 6)) * DV + (e & 63) * 4];
            }
            ppre = pg[(size_t)(tid >> 4) * Kn + kn + (tid & 15)];
        }
        // register-staged p: one LDS.128 per q row per 4-k group
#pragma unroll
        for (int k4 = 0; k4 < 4; k4++) {
            float4 pq0 = *(const float4*)&p_s[(qg + 0) * 16 + k4 * 4];
            float4 pq1 = *(const float4*)&p_s[(qg + 1) * 16 + k4 * 4];
            float4 pq2 = *(const float4*)&p_s[(qg + 2) * 16 + k4 * 4];
            float4 pq3 = *(const float4*)&p_s[(qg + 3) * 16 + k4 * 4];
            const float a0[4] = {pq0.x, pq0.y, pq0.z, pq0.w};
            const float a1[4] = {pq1.x, pq1.y, pq1.z, pq1.w};
            const float a2[4] = {pq2.x, pq2.y, pq2.z, pq2.w};
            const float a3[4] = {pq3.x, pq3.y, pq3.z, pq3.w};
#pragma unroll
            for (int kk = 0; kk < 4; kk++) {
                float4 vv = *(const float4*)&v_s[(k4 * 4 + kk) * 256 + (dvh + lane) * 4];
                acc[0].x += a0[kk] * vv.x; acc[0].y += a0[kk] * vv.y;
                acc[0].z += a0[kk] * vv.z; acc[0].w += a0[kk] * vv.w;
                acc[1].x += a1[kk] * vv.x; acc[1].y += a1[kk] * vv.y;
                acc[1].z += a1[kk] * vv.z; acc[1].w += a1[kk] * vv.w;
                acc[2].x += a2[kk] * vv.x; acc[2].y += a2[kk] * vv.y;
                acc[2].z += a2[kk] * vv.z; acc[2].w += a2[kk] * vv.w;
                acc[3].x += a3[kk] * vv.x; acc[3].y += a3[kk] * vv.y;
                acc[3].z += a3[kk] * vv.z; acc[3].w += a3[kk] * vv.w;
            }
        }
    }

    {
        float* po = g_po[ks];
#pragma unroll
        for (int r = 0; r < 4; r++)
            *(float4*)&po[(size_t)(b * Qn + q0 + qg + r) * DV + dv0 + (dvh + lane) * 4] = acc[r];
    }

    // ---- fused deterministic reduction: last CTA of the 4-way group -------
    __threadfence();
    __syncthreads();
    if (tid == 0) last_s = (atomicAdd(&g_cnt[grp], 1) == 3) ? 1 : 0;
    __syncthreads();
    if (last_s) {
        if (tid == 0) g_cnt[grp] = 0;   // reset for next graph replay
#pragma unroll
        for (int j = 0; j < 4; j++) {
            int idx = j * 256 + tid;                 // float4 idx in 16x256 region
            int r   = idx >> 6;
            int c   = idx & 63;
            size_t g = (size_t)(b * Qn + q0 + r) * (DV / 4) + (dv0 / 4) + c;
            const float4 a = ((const float4*)g_po[0])[g];
            const float4 bb = ((const float4*)g_po[1])[g];
            const float4 cc = ((const float4*)g_po[2])[g];
            const float4 dd = ((const float4*)g_po[3])[g];
            ((float4*)out)[g] = make_float4((a.x + bb.x) + (cc.x + dd.x),
                                            (a.y + bb.y) + (cc.y + dd.y),
                                            (a.z + bb.z) + (cc.z + dd.z),
                                            (a.w + bb.w) + (cc.w + dd.w));
        }
    }
}

// ---------------------------------------------------------------------------
extern "C" void kernel_launch(void* const* d_in, const int* in_sizes, int n_in,
                              void* d_out, int out_size) {
    const float* q    = (const float*)d_in[0];
    const float* k    = (const float*)d_in[1];
    const float* v    = (const float*)d_in[2];
    const int*   vlen = (const int*)d_in[3];
    const float* w_q  = (const float*)d_in[4];
    const float* w_k  = (const float*)d_in[5];
    const float* w_v  = (const float*)d_in[6];
    float*       out  = (float*)d_out;

    proj_kernel<<<640, 128>>>(q, w_q, k, w_k);
    proj_reduce_kernel<<<640, 256>>>();
    score_kernel<<<1024, 256>>>(vlen, w_v);
    softmax_kernel<<<256, 128>>>(vlen);
    pv_kernel<<<512, 256>>>(v, vlen, out);
}

// round 14
// speedup vs baseline: 1.6740x; 1.0925x over previous
#include <cuda_runtime.h>

#define B  4
#define Qn 256
#define Kn 1024
#define Dd 512
#define Hh 128
#define DV 512

#define ROWS_ALL (B * Qn + B * Kn)          // 5120 projected rows total

__device__ float g_qh[B * Qn * Hh];         // 512 KB
__device__ float g_kh[B * Kn * Hh];         // 2 MB
__device__ float g_s[B * Qn * Kn];          // 4 MB raw scores
__device__ float g_p[B * Qn * Kn];          // 4 MB normalized probs
__device__ float g_pp[2][ROWS_ALL * Hh];    // 5 MB proj K-split partials
__device__ float g_po[4][B * Qn * DV];      // 8 MB pv K-split partials
__device__ int   g_cnt_p[320];              // proj group counters (zero-init)
__device__ int   g_cnt_s[B * 16];           // score group counters (zero-init)
__device__ int   g_cnt_v[B * 16 * 2];       // pv group counters (zero-init)

__device__ __forceinline__ float ex2a(float x) {
    float r; asm("ex2.approx.f32 %0, %1;" : "=f"(r) : "f"(x)); return r;
}
__device__ __forceinline__ float tanha(float x) {
    float r; asm("tanh.approx.f32 %0, %1;" : "=f"(r) : "f"(x)); return r;
}

// ---------------------------------------------------------------------------
// Projection GEMM with fused last-CTA reduction. Grid 640 x 128, K-split 2.
// The 2 ks CTAs of a (rt,ht) tile arrive on g_cnt_p; the last loads the other
// partial at its own register-tile coords, adds (commutative, bit-exact
// either order), and writes g_qh / g_kh.
// ---------------------------------------------------------------------------
__global__ void proj_kernel(const float* __restrict__ Xq, const float* __restrict__ Wq,
                            const float* __restrict__ Xk, const float* __restrict__ Wk) {
    __shared__ float Xs[32 * 36];
    __shared__ float Ws[32 * 68];
    __shared__ int last_s;

    const int bid = blockIdx.x;
    const int rt  = bid >> 2;
    const int ht  = (bid >> 1) & 1;
    const int ks  = bid & 1;
    const int r0  = rt * 32;
    const int h0  = ht * 64;
    const int d0  = ks * 256;
    const int grp = bid >> 1;                // 0..319

    const float* Xbase = (r0 < B * Qn) ? (Xq + (size_t)r0 * Dd)
                                       : (Xk + (size_t)(r0 - B * Qn) * Dd);
    const float* W = (r0 < B * Qn) ? Wq : Wk;

    const int tid = threadIdx.x;
    const int tx  = tid & 15;
    const int ty  = tid >> 4;

    float acc[4][4];
#pragma unroll
    for (int r = 0; r < 4; r++)
#pragma unroll
        for (int c = 0; c < 4; c++) acc[r][c] = 0.0f;

    for (int s = 0; s < 8; s++) {
        const int ds = d0 + s * 32;
        __syncthreads();
#pragma unroll
        for (int i = 0; i < 2; i++) {
            int e = tid + 128 * i;
            int r = e >> 3, c4 = (e & 7) * 4;
            float4 xv = *(const float4*)&Xbase[(size_t)r * Dd + ds + c4];
            Xs[(c4 + 0) * 36 + r] = xv.x;
            Xs[(c4 + 1) * 36 + r] = xv.y;
            Xs[(c4 + 2) * 36 + r] = xv.z;
            Xs[(c4 + 3) * 36 + r] = xv.w;
        }
#pragma unroll
        for (int i = 0; i < 4; i++) {
            int e = tid + 128 * i;
            int h = e >> 3, c4 = (e & 7) * 4;
            float4 wv = *(const float4*)&W[(size_t)(h0 + h) * Dd + ds + c4];
            Ws[(c4 + 0) * 68 + h] = wv.x;
            Ws[(c4 + 1) * 68 + h] = wv.y;
            Ws[(c4 + 2) * 68 + h] = wv.z;
            Ws[(c4 + 3) * 68 + h] = wv.w;
        }
        __syncthreads();
#pragma unroll
        for (int dd = 0; dd < 32; dd++) {
            float4 xv = *(const float4*)&Xs[dd * 36 + ty * 4];
            float4 wv = *(const float4*)&Ws[dd * 68 + tx * 4];
            acc[0][0] += xv.x * wv.x; acc[0][1] += xv.x * wv.y;
            acc[0][2] += xv.x * wv.z; acc[0][3] += xv.x * wv.w;
            acc[1][0] += xv.y * wv.x; acc[1][1] += xv.y * wv.y;
            acc[1][2] += xv.y * wv.z; acc[1][3] += xv.y * wv.w;
            acc[2][0] += xv.z * wv.x; acc[2][1] += xv.z * wv.y;
            acc[2][2] += xv.z * wv.z; acc[2][3] += xv.z * wv.w;
            acc[3][0] += xv.w * wv.x; acc[3][1] += xv.w * wv.y;
            acc[3][2] += xv.w * wv.z; acc[3][3] += xv.w * wv.w;
        }
    }

    float* pp = g_pp[ks];
#pragma unroll
    for (int r = 0; r < 4; r++) {
        float4 o = make_float4(acc[r][0], acc[r][1], acc[r][2], acc[r][3]);
        *(float4*)&pp[(size_t)(r0 + ty * 4 + r) * Hh + h0 + tx * 4] = o;
    }

    __threadfence();
    __syncthreads();
    if (tid == 0) last_s = (atomicAdd(&g_cnt_p[grp], 1) == 1) ? 1 : 0;
    __syncthreads();
    if (last_s) {
        if (tid == 0) g_cnt_p[grp] = 0;      // replay-safe reset
        const float* po = g_pp[1 - ks];
        float* Out = (r0 < B * Qn) ? (g_qh + (size_t)r0 * Hh)
                                   : (g_kh + (size_t)(r0 - B * Qn) * Hh);
#pragma unroll
        for (int r = 0; r < 4; r++) {
            const int rr = ty * 4 + r;
            float4 ov = *(const float4*)&po[(size_t)(r0 + rr) * Hh + h0 + tx * 4];
            float4 o = make_float4(acc[r][0] + ov.x, acc[r][1] + ov.y,
                                   acc[r][2] + ov.z, acc[r][3] + ov.w);
            *(float4*)&Out[(size_t)rr * Hh + h0 + tx * 4] = o;
        }
    }
}

// ---------------------------------------------------------------------------
// Scores kernel with fused last-CTA softmax. Grid = 1024 CTAs, 256 threads.
// All 16 kt CTAs of a (b,qt) group (masked ones included) arrive on g_cnt_s;
// the last runs the per-warp softmax for the group's 16 q rows (warp = 2 rows
// sequentially), reading L2-hot g_s, storing probs trimmed to pv's region.
// ---------------------------------------------------------------------------
__global__ void score_kernel(const int* __restrict__ vlens,
                             const float* __restrict__ w_v) {
    __shared__ float kh_s[Hh * 65];
    __shared__ float qh_s[16 * Hh];
    __shared__ float wv_s[Hh];
    __shared__ int last_s;

    const int bx = blockIdx.x;
    const int b  = bx >> 8;
    const int qt = (bx >> 4) & 15;
    const int kt = bx & 15;
    const int q0 = qt * 16;
    const int k0 = kt * 64;
    const int grp = bx >> 4;                 // 0..63

    const int tid  = threadIdx.x;
    const int lane = tid & 31;
    const int w    = tid >> 5;
    const int vl   = vlens[b];

    if (k0 < vl) {
        {
            const float4* src = (const float4*)(g_qh + (size_t)(b * Qn + q0) * Hh);
            ((float4*)qh_s)[tid]       = src[tid];
            ((float4*)qh_s)[tid + 256] = src[tid + 256];
        }
        if (tid < Hh) wv_s[tid] = w_v[tid];

        {
            const float* khg = g_kh + (size_t)(b * Kn + k0) * Hh;
#pragma unroll
            for (int i = 0; i < 8; i++) {
                int e  = tid + 256 * i;
                int kr = e >> 5;
                int h4 = (e & 31) * 4;
                float4 vv = *(const float4*)&khg[(size_t)kr * Hh + h4];
                kh_s[(h4 + 0) * 65 + kr] = vv.x;
                kh_s[(h4 + 1) * 65 + kr] = vv.y;
                kh_s[(h4 + 2) * 65 + kr] = vv.z;
                kh_s[(h4 + 3) * 65 + kr] = vv.w;
            }
        }
        __syncthreads();

        const float* q0p = qh_s + (2 * w) * Hh;
        const float* q1p = qh_s + (2 * w + 1) * Hh;

        float s00 = 0.f, s01 = 0.f, s10 = 0.f, s11 = 0.f;
#pragma unroll 4
        for (int h = 0; h < Hh; h++) {
            float ka = kh_s[h * 65 + lane];
            float kb = kh_s[h * 65 + lane + 32];
            float qa = q0p[h];
            float qb = q1p[h];
            float wvv = wv_s[h];
            s00 += wvv * tanha(qa + ka);
            s01 += wvv * tanha(qa + kb);
            s10 += wvv * tanha(qb + ka);
            s11 += wvv * tanha(qb + kb);
        }

        float* so = g_s + (size_t)(b * Qn + q0 + 2 * w) * Kn + k0;
        so[lane]           = s00;
        so[lane + 32]      = s01;
        so[Kn + lane]      = s10;
        so[Kn + lane + 32] = s11;
        __threadfence();
    }

    // ---- group arrival; last CTA runs softmax for 16 rows ------------------
    __syncthreads();
    if (tid == 0) last_s = (atomicAdd(&g_cnt_s[grp], 1) == 15) ? 1 : 0;
    __syncthreads();
    if (!last_s) return;
    if (tid == 0) g_cnt_s[grp] = 0;          // replay-safe reset

    const int lim = (vl + 15) & ~15;         // pv read bound
#pragma unroll
    for (int rr = 0; rr < 2; rr++) {
        const int row = b * Qn + q0 + 2 * w + rr;
        const float* srow = g_s + (size_t)row * Kn;
        float e_[32];
        float m = -3.4e38f;
#pragma unroll
        for (int t = 0; t < 32; t++) {
            int k = t * 32 + lane;
            e_[t] = (k < vl) ? srow[k] : -1e6f;
            m = fmaxf(m, e_[t]);
        }
#pragma unroll
        for (int o = 16; o > 0; o >>= 1) m = fmaxf(m, __shfl_xor_sync(0xffffffffu, m, o));
        float Z = 0.f;
#pragma unroll
        for (int t = 0; t < 32; t++) {
            e_[t] = ex2a((e_[t] - m) * 1.4426950408889634f);
            Z += e_[t];
        }
#pragma unroll
        for (int o = 16; o > 0; o >>= 1) Z += __shfl_xor_sync(0xffffffffu, Z, o);
        const float invZ = 1.0f / Z;

        float* prow = g_p + (size_t)row * Kn;
#pragma unroll
        for (int t = 0; t < 32; t++) {
            if (t * 32 < lim) prow[t * 32 + lane] = e_[t] * invZ;
        }
    }
}

// ---------------------------------------------------------------------------
// Partial P@V (R13): reg-staged float4 p, 4-way parity K-split, fused
// deterministic last-CTA reduction. Grid = 512 CTAs, 256 threads.
// ---------------------------------------------------------------------------
__global__ void pv_kernel(const float* __restrict__ v, const int* __restrict__ vlens,
                          float* __restrict__ out) {
    __shared__ __align__(16) float v_s[16 * 256];   // 16 KB
    __shared__ __align__(16) float p_s[16 * 16];    // 1 KB
    __shared__ int last_s;

    const int bx  = blockIdx.x;
    const int ks  =  bx       & 3;
    const int dvs = (bx >> 2) & 1;
    const int qt  = (bx >> 3) & 15;
    const int b   =  bx >> 7;
    const int q0  = qt * 16;
    const int dv0 = dvs * 256;
    const int grp = bx >> 2;                        // 0..127

    const int tid  = threadIdx.x;
    const int lane = tid & 31;
    const int w    = tid >> 5;
    const int vl   = vlens[b];

    const int qg  = (w & 3) * 4;
    const int dvh = (w >> 2) * 32;
    const int n3  = (vl + 15) >> 4;

    const float* vb = v + (size_t)b * Kn * DV + dv0;
    const float* pg = g_p + (size_t)(b * Qn + q0) * Kn;

    float4 vpre[4];
    float  ppre;
    {
        const int k0 = ks * 16;
#pragma unroll
        for (int i = 0; i < 4; i++) {
            int e = tid + 256 * i;
            vpre[i] = *(const float4*)&vb[(size_t)(k0 + (e >> 6)) * DV + (e & 63) * 4];
        }
        ppre = pg[(size_t)(tid >> 4) * Kn + k0 + (tid & 15)];
    }

    float4 acc[4];
#pragma unroll
    for (int r = 0; r < 4; r++) acc[r] = make_float4(0.f, 0.f, 0.f, 0.f);

    for (int t = ks; t < n3; t += 4) {
        __syncthreads();
#pragma unroll
        for (int i = 0; i < 4; i++) {
            int e = tid + 256 * i;
            *(float4*)&v_s[(e >> 6) * 256 + (e & 63) * 4] = vpre[i];
        }
        p_s[(tid >> 4) * 16 + (tid & 15)] = ppre;
        __syncthreads();
        if (t + 4 < n3) {
            const int kn = (t + 4) * 16;
#pragma unroll
            for (int i = 0; i < 4; i++) {
                int e = tid + 256 * i;
                vpre[i] = *(const float4*)&vb[(size_t)(kn + (e >> 6)) * DV + (e & 63) * 4];
            }
            ppre = pg[(size_t)(tid >> 4) * Kn + kn + (tid & 15)];
        }
#pragma unroll
        for (int k4 = 0; k4 < 4; k4++) {
            float4 pq0 = *(const float4*)&p_s[(qg + 0) * 16 + k4 * 4];
            float4 pq1 = *(const float4*)&p_s[(qg + 1) * 16 + k4 * 4];
            float4 pq2 = *(const float4*)&p_s[(qg + 2) * 16 + k4 * 4];
            float4 pq3 = *(const float4*)&p_s[(qg + 3) * 16 + k4 * 4];
            const float a0[4] = {pq0.x, pq0.y, pq0.z, pq0.w};
            const float a1[4] = {pq1.x, pq1.y, pq1.z, pq1.w};
            const float a2[4] = {pq2.x, pq2.y, pq2.z, pq2.w};
            const float a3[4] = {pq3.x, pq3.y, pq3.z, pq3.w};
#pragma unroll
            for (int kk = 0; kk < 4; kk++) {
                float4 vv = *(const float4*)&v_s[(k4 * 4 + kk) * 256 + (dvh + lane) * 4];
                acc[0].x += a0[kk] * vv.x; acc[0].y += a0[kk] * vv.y;
                acc[0].z += a0[kk] * vv.z; acc[0].w += a0[kk] * vv.w;
                acc[1].x += a1[kk] * vv.x; acc[1].y += a1[kk] * vv.y;
                acc[1].z += a1[kk] * vv.z; acc[1].w += a1[kk] * vv.w;
                acc[2].x += a2[kk] * vv.x; acc[2].y += a2[kk] * vv.y;
                acc[2].z += a2[kk] * vv.z; acc[2].w += a2[kk] * vv.w;
                acc[3].x += a3[kk] * vv.x; acc[3].y += a3[kk] * vv.y;
                acc[3].z += a3[kk] * vv.z; acc[3].w += a3[kk] * vv.w;
            }
        }
    }

    {
        float* po = g_po[ks];
#pragma unroll
        for (int r = 0; r < 4; r++)
            *(float4*)&po[(size_t)(b * Qn + q0 + qg + r) * DV + dv0 + (dvh + lane) * 4] = acc[r];
    }

    __threadfence();
    __syncthreads();
    if (tid == 0) last_s = (atomicAdd(&g_cnt_v[grp], 1) == 3) ? 1 : 0;
    __syncthreads();
    if (last_s) {
        if (tid == 0) g_cnt_v[grp] = 0;   // replay-safe reset
#pragma unroll
        for (int j = 0; j < 4; j++) {
            int idx = j * 256 + tid;
            int r   = idx >> 6;
            int c   = idx & 63;
            size_t g = (size_t)(b * Qn + q0 + r) * (DV / 4) + (dv0 / 4) + c;
            const float4 a = ((const float4*)g_po[0])[g];
            const float4 bb = ((const float4*)g_po[1])[g];
            const float4 cc = ((const float4*)g_po[2])[g];
            const float4 dd = ((const float4*)g_po[3])[g];
            ((float4*)out)[g] = make_float4((a.x + bb.x) + (cc.x + dd.x),
                                            (a.y + bb.y) + (cc.y + dd.y),
                                            (a.z + bb.z) + (cc.z + dd.z),
                                            (a.w + bb.w) + (cc.w + dd.w));
        }
    }
}

// ---------------------------------------------------------------------------
extern "C" void kernel_launch(void* const* d_in, const int* in_sizes, int n_in,
                              void* d_out, int out_size) {
    const float* q    = (const float*)d_in[0];
    const float* k    = (const float*)d_in[1];
    const float* v    = (const float*)d_in[2];
    const int*   vlen = (const int*)d_in[3];
    const float* w_q  = (const float*)d_in[4];
    const float* w_k  = (const float*)d_in[5];
    const float* w_v  = (const float*)d_in[6];
    float*       out  = (float*)d_out;

    proj_kernel<<<640, 128>>>(q, w_q, k, w_k);
    score_kernel<<<1024, 256>>>(vlen, w_v);
    pv_kernel<<<512, 256>>>(v, vlen, out);
}